// round 1
// baseline (speedup 1.0000x reference)
#include <cuda_runtime.h>
#include <cstddef>

#define TILE_N 32
#define KC 32

// -------- scratch (fixed problem sizes: N2=16384, N1=65536, Cout=64) --------
__device__ float g_y2t[16384 * 192];   // y2 transposed: [N2][C*3], 12.6 MB
__device__ int   g_idx[65536 * 3];     // global coarse row index per (fine,k)
__device__ float g_w  [65536 * 3];     // normalized inverse-dist weights

// ---------------------------------------------------------------------------
// kNN: brute force top-3 per fine point over its batch's coarse segment.
// Ranking metric m = 0.5*|s|^2 - q.s  (monotone in |q-s|^2 for fixed q).
// Exact d2 recomputed for the 3 winners to match reference weights.
// ---------------------------------------------------------------------------
__global__ __launch_bounds__(256)
void knn_kernel(const float* __restrict__ p1, const float* __restrict__ p2,
                int n1, int n2, int N1)
{
    __shared__ float4 sref[1024];
    const int tid = threadIdx.x;
    const int q = blockIdx.x * 256 + tid;
    const int batch = (blockIdx.x * 256) / n1;   // 256 | n1 (16384)
    const int base = batch * n2;

    float qx = 0.f, qy = 0.f, qz = 0.f;
    if (q < N1) { qx = p1[3*q]; qy = p1[3*q+1]; qz = p1[3*q+2]; }

    float m0 = 3.4e38f, m1 = 3.4e38f, m2 = 3.4e38f;
    int i0 = 0, i1 = 0, i2 = 0;

    for (int t0 = 0; t0 < n2; t0 += 1024) {
        __syncthreads();
        for (int j = tid; j < 1024; j += 256) {
            if (t0 + j < n2) {
                const float* s = p2 + (size_t)3 * (base + t0 + j);
                float sx = s[0], sy = s[1], sz = s[2];
                sref[j] = make_float4(sx, sy, sz, 0.5f*(sx*sx + sy*sy + sz*sz));
            }
        }
        __syncthreads();
        const int cnt = min(1024, n2 - t0);
#pragma unroll 4
        for (int j = 0; j < cnt; j++) {
            float4 s = sref[j];
            float m = fmaf(-qx, s.x, fmaf(-qy, s.y, fmaf(-qz, s.z, s.w)));
            if (m < m2) {
                int jj = t0 + j;
                if (m < m1) {
                    m2 = m1; i2 = i1;
                    if (m < m0) { m1 = m0; i1 = i0; m0 = m; i0 = jj; }
                    else        { m1 = m;  i1 = jj; }
                } else { m2 = m; i2 = jj; }
            }
        }
    }

    if (q < N1) {
        int id[3] = { i0, i1, i2 };
        float w[3], wsum = 0.f;
#pragma unroll
        for (int k = 0; k < 3; k++) {
            const float* s = p2 + (size_t)3 * (base + id[k]);
            float dx = qx - s[0], dy = qy - s[1], dz = qz - s[2];
            float d2 = dx*dx + dy*dy + dz*dz;     // exact, matches reference
            w[k] = 1.f / (d2 + 1e-8f);
            wsum += w[k];
        }
        float inv = 1.f / wsum;
#pragma unroll
        for (int k = 0; k < 3; k++) {
            g_idx[q*3 + k] = base + id[k];
            g_w[q*3 + k]   = w[k] * inv;
        }
    }
}

// ---------------------------------------------------------------------------
// VN linear + leaky-ReLU.
//   p = Wf @ x,  d = Wd @ x  (per point, per vector comp)
//   out = p                       if dot(p,d) >= 0
//       = p - 0.8*dot/(|d|^2+eps)*d   otherwise
// FUSE=false: writes y2 transposed to g_y2t[n][o*3+v]   (interp source)
// FUSE=true : adds 3-NN interpolation of g_y2t and writes out[(o*3+v)*N + n]
//
// Block: 256 threads, 32-point tile. Thread = (og=tid&15 -> o_base=4*og,
// pg=tid>>4 -> pt_base=2*pg). Each thread: 4 o x 2 pts x 3 comps for p and d.
// Weights staged transposed in smem, stride 68 (float4-aligned, conflict-free
// reads). x staged [KC*3][32].
// ---------------------------------------------------------------------------
template<int CIN, bool FUSE>
__global__ __launch_bounds__(256, 2)
void vn_kernel(const float* __restrict__ x, const float* __restrict__ wfeat,
               const float* __restrict__ wdir, int N, float* __restrict__ out)
{
    __shared__ __align__(16) float swf[KC * 68];
    __shared__ __align__(16) float swd[KC * 68];
    __shared__ __align__(16) float xs [KC * 96];
    __shared__ int   sidx[TILE_N * 3];
    __shared__ float swt [TILE_N * 3];

    const int tid = threadIdx.x;
    const int o_base  = (tid & 15) * 4;
    const int pt_base = (tid >> 4) * 2;
    const int n0 = blockIdx.x * TILE_N;
    const int lane = tid & 31;
    const int wrow = tid >> 5;

    if (FUSE && tid < 96) {
        sidx[tid] = g_idx[n0*3 + tid];
        swt[tid]  = g_w[n0*3 + tid];
    }

    float p[24], q[24];
#pragma unroll
    for (int i = 0; i < 24; i++) { p[i] = 0.f; q[i] = 0.f; }

    for (int c0 = 0; c0 < CIN; c0 += KC) {
        __syncthreads();
        // stage weights transposed: swf[cc*68 + o] = wfeat[o*CIN + c0+cc]
        for (int i = tid; i < 64 * KC; i += 256) {
            int o  = i >> 5;     // i / KC, KC=32
            int cc = i & 31;
            swf[cc*68 + o] = wfeat[o*CIN + c0 + cc];
            swd[cc*68 + o] = wdir [o*CIN + c0 + cc];
        }
        // stage x tile: rows r = (c-c0)*3+v, cols = local point
        const float* xg = x + (size_t)(c0 * 3) * N + n0;
        for (int r = wrow; r < KC * 3; r += 8)
            xs[r * TILE_N + lane] = xg[(size_t)r * N + lane];
        __syncthreads();

#pragma unroll 8
        for (int cc = 0; cc < KC; ++cc) {
            const float4 f4 = *reinterpret_cast<const float4*>(&swf[cc*68 + o_base]);
            const float4 g4 = *reinterpret_cast<const float4*>(&swd[cc*68 + o_base]);
            const float2 xa = *reinterpret_cast<const float2*>(&xs[(cc*3+0)*TILE_N + pt_base]);
            const float2 xb = *reinterpret_cast<const float2*>(&xs[(cc*3+1)*TILE_N + pt_base]);
            const float2 xc = *reinterpret_cast<const float2*>(&xs[(cc*3+2)*TILE_N + pt_base]);
            float wf[4] = { f4.x, f4.y, f4.z, f4.w };
            float wg[4] = { g4.x, g4.y, g4.z, g4.w };
            float xv[2][3] = { { xa.x, xb.x, xc.x }, { xa.y, xb.y, xc.y } };
#pragma unroll
            for (int i = 0; i < 4; i++)
#pragma unroll
                for (int k = 0; k < 2; k++)
#pragma unroll
                    for (int v = 0; v < 3; v++) {
                        p[(i*2+k)*3+v] = fmaf(wf[i], xv[k][v], p[(i*2+k)*3+v]);
                        q[(i*2+k)*3+v] = fmaf(wg[i], xv[k][v], q[(i*2+k)*3+v]);
                    }
        }
    }

    // VN leaky-ReLU, in place into p
#pragma unroll
    for (int i = 0; i < 4; i++)
#pragma unroll
        for (int k = 0; k < 2; k++) {
            const int s = (i*2 + k) * 3;
            float px = p[s], py = p[s+1], pz = p[s+2];
            float dx = q[s], dy = q[s+1], dz = q[s+2];
            float dot = px*dx + py*dy + pz*dz;
            if (dot < 0.f) {
                float d2 = dx*dx + dy*dy + dz*dz;
                float t = 0.8f * dot / (d2 + 1e-6f);
                p[s]   = px - t*dx;
                p[s+1] = py - t*dy;
                p[s+2] = pz - t*dz;
            }
        }

    if (FUSE) {
        // add 3-NN interpolation from L2-resident g_y2t (contiguous 48B slices)
#pragma unroll
        for (int k = 0; k < 2; k++) {
            const int pt = pt_base + k;
#pragma unroll
            for (int kk = 0; kk < 3; kk++) {
                const int row = sidx[pt*3 + kk];
                const float w = swt[pt*3 + kk];
                const float4* src = reinterpret_cast<const float4*>(
                    g_y2t + (size_t)row * 192 + o_base * 3);
                float4 A = src[0], B = src[1], C = src[2];
                p[ 0 + 3*k + 0] += w * A.x;
                p[ 0 + 3*k + 1] += w * A.y;
                p[ 0 + 3*k + 2] += w * A.z;
                p[ 6 + 3*k + 0] += w * A.w;
                p[ 6 + 3*k + 1] += w * B.x;
                p[ 6 + 3*k + 2] += w * B.y;
                p[12 + 3*k + 0] += w * B.z;
                p[12 + 3*k + 1] += w * B.w;
                p[12 + 3*k + 2] += w * C.x;
                p[18 + 3*k + 0] += w * C.y;
                p[18 + 3*k + 1] += w * C.z;
                p[18 + 3*k + 2] += w * C.w;
            }
        }
        // store [Cout,3,N] layout
#pragma unroll
        for (int i = 0; i < 4; i++)
#pragma unroll
            for (int k = 0; k < 2; k++)
#pragma unroll
                for (int v = 0; v < 3; v++)
                    out[(size_t)((o_base + i)*3 + v) * N + n0 + pt_base + k]
                        = p[(i*2+k)*3 + v];
    } else {
        // store transposed: g_y2t[n][o*3+v]
#pragma unroll
        for (int k = 0; k < 2; k++) {
            float* dst = g_y2t + (size_t)(n0 + pt_base + k) * 192 + o_base * 3;
#pragma unroll
            for (int i = 0; i < 4; i++)
#pragma unroll
                for (int v = 0; v < 3; v++)
                    dst[i*3 + v] = p[(i*2+k)*3 + v];
        }
    }
}

// ---------------------------------------------------------------------------
extern "C" void kernel_launch(void* const* d_in, const int* in_sizes, int n_in,
                              void* d_out, int out_size)
{
    (void)n_in; (void)out_size;
    const float* p1  = (const float*)d_in[0];
    const float* x1  = (const float*)d_in[1];
    const float* p2  = (const float*)d_in[3];
    const float* x2  = (const float*)d_in[4];
    const float* w1f = (const float*)d_in[6];
    const float* w1d = (const float*)d_in[7];
    const float* w2f = (const float*)d_in[8];
    const float* w2d = (const float*)d_in[9];

    const int b  = in_sizes[2];
    const int N1 = in_sizes[0] / 3;
    const int N2 = in_sizes[3] / 3;
    const int n1 = N1 / b;
    const int n2 = N2 / b;
    float* out = (float*)d_out;

    // 1) kNN (independent of the GEMMs)
    knn_kernel<<<(N1 + 255) / 256, 256>>>(p1, p2, n1, n2, N1);

    // 2) vn2: x2 -> y2 transposed scratch  (Cin=128)
    vn_kernel<128, false><<<N2 / TILE_N, 256>>>(x2, w2f, w2d, N2, nullptr);

    // 3) vn1 + fused interpolation add -> out  (Cin=64)
    vn_kernel<64, true><<<N1 / TILE_N, 256>>>(x1, w1f, w1d, N1, out);
}